// round 6
// baseline (speedup 1.0000x reference)
#include <cuda_runtime.h>
#include <cstdint>
#include <math_constants.h>

#define A_NUM 9
#define H_DIM 128
#define W_DIM 192
#define HW (H_DIM*W_DIM)            // 24576
#define NTOT (HW*A_NUM)             // 221184
#define PRE_NMS 6000
#define POST_NMS 300
#define NBINS 4096
#define CAND_CAP 8192
#define MASK_WORDS ((PRE_NMS+63)/64)   // 94
#define VWORDS (2*MASK_WORDS)          // 188 u32
#define NMS_THR 0.7f
#define PREP_BLOCKS (NTOT/256)         // 864
#define SBOX_N 2048                    // candidate boxes preloaded to smem

__constant__ float c_anchors[A_NUM][4] = {
    {-84.f,  -40.f,  99.f,  55.f},
    {-176.f, -88.f,  191.f, 103.f},
    {-360.f, -184.f, 375.f, 199.f},
    {-56.f,  -56.f,  71.f,  71.f},
    {-120.f, -120.f, 135.f, 135.f},
    {-248.f, -248.f, 263.f, 263.f},
    {-36.f,  -80.f,  51.f,  95.f},
    {-80.f,  -168.f, 95.f,  183.f},
    {-168.f, -344.f, 183.f, 359.f}};

__device__ float4 g_boxes[NTOT];          // [a][p] layout
__device__ float  g_scores[NTOT];         // [a][p] layout
__device__ int    g_hist[NBINS];          // starts zero; self-cleaning
__device__ int    g_thr;
__device__ int    g_numCand;
__device__ int    g_done = 0;
__device__ unsigned long long g_candKeys[CAND_CAP];
__device__ float4 g_boxesS[PRE_NMS];
__device__ unsigned int g_validbits[VWORDS];

// ============================================================ 1. decode + hist + threshold
__global__ void k_prep(const float* __restrict__ scores,
                       const float* __restrict__ deltas,
                       const float* __restrict__ im_info) {
    int g = blockIdx.x * blockDim.x + threadIdx.x;
    int a = g / HW;
    int p = g - a * HW;
    int x = p % W_DIM;
    int y = p / W_DIM;

    float sc = scores[(A_NUM + a) * HW + p];
    float dx = deltas[(4 * a + 0) * HW + p];
    float dy = deltas[(4 * a + 1) * HW + p];
    float dw = deltas[(4 * a + 2) * HW + p];
    float dh = deltas[(4 * a + 3) * HW + p];
    dw = fminf(fmaxf(dw, -10.f), 10.f);
    dh = fminf(fmaxf(dh, -10.f), 10.f);

    float sx = (float)x * 16.f;
    float sy = (float)y * 16.f;
    float ax1 = c_anchors[a][0] + sx;
    float ay1 = c_anchors[a][1] + sy;
    float ax2 = c_anchors[a][2] + sx;
    float ay2 = c_anchors[a][3] + sy;
    float wdt = ax2 - ax1 + 1.f;
    float hgt = ay2 - ay1 + 1.f;
    float cx = ax1 + 0.5f * wdt;
    float cy = ay1 + 0.5f * hgt;

    float pcx = dx * wdt + cx;
    float pcy = dy * hgt + cy;
    float pw = expf(dw) * wdt;
    float ph = expf(dh) * hgt;

    float imH = __ldg(&im_info[0]), imW = __ldg(&im_info[1]), sc_im = __ldg(&im_info[2]);
    float x1 = pcx - 0.5f * pw;
    float y1 = pcy - 0.5f * ph;
    float x2 = pcx + 0.5f * pw;
    float y2 = pcy + 0.5f * ph;
    x1 = fminf(fmaxf(x1, 0.f), imW - 1.f);
    x2 = fminf(fmaxf(x2, 0.f), imW - 1.f);
    y1 = fminf(fmaxf(y1, 0.f), imH - 1.f);
    y2 = fminf(fmaxf(y2, 0.f), imH - 1.f);

    g_boxes[g] = make_float4(x1, y1, x2, y2);
    float minsz = 16.f * sc_im;
    bool valid = (x2 - x1 + 1.f >= minsz) && (y2 - y1 + 1.f >= minsz);
    g_scores[g] = valid ? sc : -CUDART_INF_F;
    if (valid) {
        int bin = (int)(sc * (float)NBINS);
        bin = max(0, min(NBINS - 1, bin));
        atomicAdd(&g_hist[bin], 1);
    }

    // ---- last-block threshold computation ----
    __shared__ int s_last;
    __shared__ int sh[NBINS];
    __shared__ int csum[256];
    __syncthreads();
    if (threadIdx.x == 0) {
        __threadfence();
        int v = atomicAdd(&g_done, 1);
        s_last = (v == PREP_BLOCKS - 1);
    }
    __syncthreads();
    if (!s_last) return;

    int t = threadIdx.x;
    int base = t * 16;
    int sum = 0;
    #pragma unroll
    for (int k = 0; k < 16; k++) {
        int v = g_hist[base + k];
        sh[base + k] = v;
        g_hist[base + k] = 0;         // re-zero for next run
        sum += v;
    }
    csum[t] = sum;
    if (t < VWORDS) g_validbits[t] = 0u;
    __syncthreads();
    if (t == 0) {
        int cum = 0, thr = 0;
        int c = 255;
        for (; c >= 0; c--) {
            if (cum + csum[c] >= PRE_NMS) break;
            cum += csum[c];
        }
        if (c >= 0) {
            for (int b = c * 16 + 15; b >= c * 16; b--) {
                cum += sh[b];
                if (cum >= PRE_NMS) { thr = b; break; }
            }
        }
        g_thr = thr;
        g_numCand = 0;
        g_done = 0;
    }
}

// ============================================================ 2. candidate compaction
__global__ void k_filter() {
    int g = blockIdx.x * blockDim.x + threadIdx.x;
    float s = g_scores[g];
    if (!(s >= 0.0f)) return;          // invalid -> -inf (scores are in [0,1))
    int bin = (int)(s * (float)NBINS);
    bin = max(0, min(NBINS - 1, bin));
    if (bin < g_thr) return;
    int pos = atomicAdd(&g_numCand, 1);
    if (pos < CAND_CAP) {
        int a = g / HW;
        int p = g - a * HW;
        unsigned i_orig = (unsigned)(p * A_NUM + a);   // reference flatten order
        unsigned long long key =
            ((unsigned long long)__float_as_uint(s) << 32) |
            (unsigned long long)(~i_orig);
        g_candKeys[pos] = key;
    }
}

// ============================================================ 3. ranking sort + gather
__global__ void k_rank() {
    __shared__ unsigned long long tile[2048];
    int i = blockIdx.x * blockDim.x + threadIdx.x;
    int n = min(g_numCand, CAND_CAP);
    bool active = (i < n);
    unsigned long long my = active ? g_candKeys[i] : 0ULL;
    int rank = 0;
    for (int base = 0; base < n; base += 2048) {
        int cnt = min(2048, n - base);
        for (int j = threadIdx.x; j < cnt; j += blockDim.x)
            tile[j] = g_candKeys[base + j];
        __syncthreads();
        if (active) {
            #pragma unroll 8
            for (int j = 0; j < cnt; j++)
                rank += (tile[j] > my) ? 1 : 0;
        }
        __syncthreads();
    }
    if (active && rank < PRE_NMS) {
        unsigned idx = ~(unsigned)(my & 0xffffffffULL);   // i_orig = p*9+a
        int a = (int)(idx % A_NUM);
        int p = (int)(idx / A_NUM);
        g_boxesS[rank] = g_boxes[a * HW + p];
        atomicOr(&g_validbits[rank >> 5], 1u << (rank & 31));
    }
}

// ============================================================ 4. direct greedy NMS (one warp scans)
__global__ void k_nms(float* __restrict__ out) {
    __shared__ float4 sbox[SBOX_N];
    __shared__ float4 skept[POST_NMS];
    __shared__ float  skarea[POST_NMS];
    __shared__ unsigned long long svb[MASK_WORDS];

    int tid = threadIdx.x;
    // cooperative preload: 256 threads
    for (int i = tid; i < SBOX_N; i += 256)
        sbox[i] = g_boxesS[i];
    if (tid < MASK_WORDS)
        svb[tid] = ((unsigned long long)g_validbits[2 * tid + 1] << 32) |
                   (unsigned long long)g_validbits[2 * tid];
    __syncthreads();
    if (tid >= 32) return;     // only warp 0 continues; no more block syncs

    int lane = tid;
    int kc = 0;                // uniform across warp
    for (int w = 0; w < MASK_WORDS && kc < POST_NMS; w++) {
        unsigned long long bits = svb[w];   // uniform (same smem word)
        while (bits) {
            int ib = __ffsll(bits) - 1;
            bits &= bits - 1;
            int i = w * 64 + ib;
            float4 b = (i < SBOX_N) ? sbox[i] : __ldg(&g_boxesS[i]);
            float areaI = (b.z - b.x) * (b.w - b.y);
            bool flag = false;
            for (int k = lane; k < kc; k += 32) {
                float4 kb = skept[k];
                float lx = fmaxf(b.x, kb.x);
                float ly = fmaxf(b.y, kb.y);
                float rx = fminf(b.z, kb.z);
                float ry = fminf(b.w, kb.w);
                float ww = fmaxf(rx - lx, 0.f);
                float hh = fmaxf(ry - ly, 0.f);
                float inter = ww * hh;
                float iou = inter / (areaI + skarea[k] - inter);
                flag |= (iou > NMS_THR);
            }
            bool supp = __any_sync(0xffffffffu, flag);
            if (!supp) {
                if (lane == 0) {
                    skept[kc] = b;
                    skarea[kc] = areaI;
                    out[kc * 5 + 0] = 0.f;
                    out[kc * 5 + 1] = b.x;
                    out[kc * 5 + 2] = b.y;
                    out[kc * 5 + 3] = b.z;
                    out[kc * 5 + 4] = b.w;
                }
                kc++;                       // uniform
                __syncwarp();               // make skept/skarea visible
                if (kc >= POST_NMS) break;
            }
        }
    }
    __syncwarp();
    // zero-fill remaining rows (kc uniform)
    for (int x = kc * 5 + lane; x < POST_NMS * 5; x += 32) out[x] = 0.f;
}

// ============================================================ launch
extern "C" void kernel_launch(void* const* d_in, const int* in_sizes, int n_in,
                              void* d_out, int out_size) {
    const float* scores  = (const float*)d_in[0];
    const float* deltas  = (const float*)d_in[1];
    const float* im_info = (const float*)d_in[2];
    float* out = (float*)d_out;

    k_prep<<<PREP_BLOCKS, 256>>>(scores, deltas, im_info);
    k_filter<<<PREP_BLOCKS, 256>>>();
    k_rank<<<CAND_CAP / 64, 64>>>();
    k_nms<<<1, 256>>>(out);
}

// round 7
// speedup vs baseline: 3.5299x; 3.5299x over previous
#include <cuda_runtime.h>
#include <cstdint>
#include <math_constants.h>

#define A_NUM 9
#define H_DIM 128
#define W_DIM 192
#define HW (H_DIM*W_DIM)            // 24576
#define NTOT (HW*A_NUM)             // 221184
#define PRE_NMS 6000
#define POST_NMS 300
#define NBINS 4096
#define CAND_CAP 8192
#define MASK_WORDS ((PRE_NMS+63)/64)   // 94 (validbits words)
#define VWORDS (2*MASK_WORDS)          // 188 u32
#define NMS_THR 0.7f
#define PREP_BLOCKS (NTOT/256)         // 864
#define PREFIX 1536
#define PWORDS (PREFIX/64)             // 24
#define PGRID (PWORDS*PWORDS)          // 576
#define RANK_BLOCKS 128
#define RANK_T 64
#define RANK_THREADS (RANK_BLOCKS*RANK_T)  // 8192

__constant__ float c_anchors[A_NUM][4] = {
    {-84.f,  -40.f,  99.f,  55.f},
    {-176.f, -88.f,  191.f, 103.f},
    {-360.f, -184.f, 375.f, 199.f},
    {-56.f,  -56.f,  71.f,  71.f},
    {-120.f, -120.f, 135.f, 135.f},
    {-248.f, -248.f, 263.f, 263.f},
    {-36.f,  -80.f,  51.f,  95.f},
    {-80.f,  -168.f, 95.f,  183.f},
    {-168.f, -344.f, 183.f, 359.f}};

__device__ float4 g_boxes[NTOT];          // [a][p] layout
__device__ float  g_scores[NTOT];         // [a][p] layout
__device__ int    g_hist[NBINS];          // starts zero; self-cleaning
__device__ int    g_thr;
__device__ int    g_numCand;
__device__ int    g_done  = 0;
__device__ int    g_done2 = 0;
__device__ int    g_sync1 = 0;
__device__ unsigned long long g_candKeys[CAND_CAP];
__device__ float4 g_boxesS[PRE_NMS];
__device__ unsigned int g_validbits[VWORDS];
__device__ unsigned long long g_maskP[PREFIX * PWORDS];

// ============================================================ 1. decode + hist + threshold
__global__ void k_prep(const float* __restrict__ scores,
                       const float* __restrict__ deltas,
                       const float* __restrict__ im_info) {
    int g = blockIdx.x * blockDim.x + threadIdx.x;
    int a = g / HW;
    int p = g - a * HW;
    int x = p % W_DIM;
    int y = p / W_DIM;

    float sc = scores[(A_NUM + a) * HW + p];
    float dx = deltas[(4 * a + 0) * HW + p];
    float dy = deltas[(4 * a + 1) * HW + p];
    float dw = deltas[(4 * a + 2) * HW + p];
    float dh = deltas[(4 * a + 3) * HW + p];
    dw = fminf(fmaxf(dw, -10.f), 10.f);
    dh = fminf(fmaxf(dh, -10.f), 10.f);

    float sx = (float)x * 16.f;
    float sy = (float)y * 16.f;
    float ax1 = c_anchors[a][0] + sx;
    float ay1 = c_anchors[a][1] + sy;
    float ax2 = c_anchors[a][2] + sx;
    float ay2 = c_anchors[a][3] + sy;
    float wdt = ax2 - ax1 + 1.f;
    float hgt = ay2 - ay1 + 1.f;
    float cx = ax1 + 0.5f * wdt;
    float cy = ay1 + 0.5f * hgt;

    float pcx = dx * wdt + cx;
    float pcy = dy * hgt + cy;
    float pw = expf(dw) * wdt;
    float ph = expf(dh) * hgt;

    float imH = __ldg(&im_info[0]), imW = __ldg(&im_info[1]), sc_im = __ldg(&im_info[2]);
    float x1 = pcx - 0.5f * pw;
    float y1 = pcy - 0.5f * ph;
    float x2 = pcx + 0.5f * pw;
    float y2 = pcy + 0.5f * ph;
    x1 = fminf(fmaxf(x1, 0.f), imW - 1.f);
    x2 = fminf(fmaxf(x2, 0.f), imW - 1.f);
    y1 = fminf(fmaxf(y1, 0.f), imH - 1.f);
    y2 = fminf(fmaxf(y2, 0.f), imH - 1.f);

    g_boxes[g] = make_float4(x1, y1, x2, y2);
    float minsz = 16.f * sc_im;
    bool valid = (x2 - x1 + 1.f >= minsz) && (y2 - y1 + 1.f >= minsz);
    g_scores[g] = valid ? sc : -CUDART_INF_F;
    if (valid) {
        int bin = (int)(sc * (float)NBINS);
        bin = max(0, min(NBINS - 1, bin));
        atomicAdd(&g_hist[bin], 1);
    }

    // ---- last-block threshold computation ----
    __shared__ int s_last;
    __shared__ int sh[NBINS];
    __shared__ int csum[256];
    __syncthreads();
    if (threadIdx.x == 0) {
        __threadfence();
        int v = atomicAdd(&g_done, 1);
        s_last = (v == PREP_BLOCKS - 1);
    }
    __syncthreads();
    if (!s_last) return;

    int t = threadIdx.x;
    int base = t * 16;
    int sum = 0;
    #pragma unroll
    for (int k = 0; k < 16; k++) {
        int v = g_hist[base + k];
        sh[base + k] = v;
        g_hist[base + k] = 0;         // re-zero for next run
        sum += v;
    }
    csum[t] = sum;
    if (t < VWORDS) g_validbits[t] = 0u;
    __syncthreads();
    if (t == 0) {
        int cum = 0, thr = 0;
        int c = 255;
        for (; c >= 0; c--) {
            if (cum + csum[c] >= PRE_NMS) break;
            cum += csum[c];
        }
        if (c >= 0) {
            for (int b = c * 16 + 15; b >= c * 16; b--) {
                cum += sh[b];
                if (cum >= PRE_NMS) { thr = b; break; }
            }
        }
        g_thr = thr;
        g_numCand = 0;
        g_done  = 0;
        g_sync1 = 0;
    }
}

// ============================================================ 2. filter + grid-barrier + ranking sort + gather
__global__ void k_rank() {
    int tid = blockIdx.x * RANK_T + threadIdx.x;

    // ---- filter phase: grid-stride over all anchors ----
    int thr = g_thr;
    for (int g = tid; g < NTOT; g += RANK_THREADS) {
        float s = g_scores[g];
        if (s >= 0.0f) {
            int bin = min(NBINS - 1, (int)(s * (float)NBINS));
            if (bin >= thr) {
                int pos = atomicAdd(&g_numCand, 1);
                if (pos < CAND_CAP) {
                    int a = g / HW;
                    int p = g - a * HW;
                    unsigned i_orig = (unsigned)(p * A_NUM + a);  // reference flatten order
                    unsigned long long key =
                        ((unsigned long long)__float_as_uint(s) << 32) |
                        (unsigned long long)(~i_orig);
                    g_candKeys[pos] = key;
                }
            }
        }
    }

    // ---- software grid barrier (128 blocks, all co-resident) ----
    __threadfence();
    __syncthreads();
    if (threadIdx.x == 0) {
        atomicAdd(&g_sync1, 1);
        while (atomicAdd(&g_sync1, 0) < RANK_BLOCKS) { }
    }
    __syncthreads();

    // ---- rank phase ----
    __shared__ unsigned long long tile[2048];
    int n = min(g_numCand, CAND_CAP);
    bool active = (tid < n);
    unsigned long long my = active ? g_candKeys[tid] : 0ULL;
    int rank = 0;
    for (int base = 0; base < n; base += 2048) {
        int cnt = min(2048, n - base);
        for (int j = threadIdx.x; j < cnt; j += RANK_T)
            tile[j] = g_candKeys[base + j];
        __syncthreads();
        if (active) {
            #pragma unroll 8
            for (int j = 0; j < cnt; j++)
                rank += (tile[j] > my) ? 1 : 0;
        }
        __syncthreads();
    }
    if (active && rank < PRE_NMS) {
        unsigned idx = ~(unsigned)(my & 0xffffffffULL);   // i_orig = p*9+a
        int a = (int)(idx % A_NUM);
        int p = (int)(idx / A_NUM);
        g_boxesS[rank] = g_boxes[a * HW + p];
        atomicOr(&g_validbits[rank >> 5], 1u << (rank & 31));
    }
}

// ============================================================ 3. prefix mask + (last block) scan + fallback
__global__ void k_mask_scan(float* __restrict__ out) {
    int bi = blockIdx.y;
    int bj = blockIdx.x;
    int t = threadIdx.x;
    __shared__ float4 jb[64];

    bool work = (bj >= bi);
    if (work) {
        jb[t] = g_boxesS[bj * 64 + t];
    }
    __syncthreads();
    if (work) {
        int i = bi * 64 + t;
        int jbase = bj * 64;
        float4 b1 = g_boxesS[i];
        float areaI = (b1.z - b1.x) * (b1.w - b1.y);
        unsigned long long bits = 0ULL;
        bool diag = (bi == bj);
        #pragma unroll 4
        for (int j = 0; j < 64; j++) {
            if (diag && jbase + j <= i) continue;
            float4 b2 = jb[j];
            float lx = fmaxf(b1.x, b2.x);
            float ly = fmaxf(b1.y, b2.y);
            float rx = fminf(b1.z, b2.z);
            float ry = fminf(b1.w, b2.w);
            float w = fmaxf(rx - lx, 0.f);
            float h = fmaxf(ry - ly, 0.f);
            float inter = w * h;
            if (inter > 0.f) {
                float areaJ = (b2.z - b2.x) * (b2.w - b2.y);
                float iou = inter / (areaI + areaJ - inter);
                if (iou > NMS_THR) bits |= (1ULL << j);
            }
        }
        g_maskP[(size_t)i * PWORDS + bj] = bits;
    }

    // ---- completion protocol ----
    __shared__ int s_last;
    __syncthreads();
    if (t == 0) {
        __threadfence();
        int v = atomicAdd(&g_done2, 1);
        s_last = (v == PGRID - 1);
    }
    __syncthreads();
    if (!s_last) return;
    if (t == 0) g_done2 = 0;
    if (t >= 32) return;

    // ---- greedy NMS scan on warp 0 of the last block ----
    __shared__ unsigned long long remv[PWORDS];
    __shared__ unsigned long long svb[MASK_WORDS];
    __shared__ unsigned long long colbuf[2][64];
    __shared__ float4 colbox[2][64];
    __shared__ float4 skept[POST_NMS];
    __shared__ float  skarea[POST_NMS];
    __shared__ int s_kept[64];
    __shared__ int s_nk, s_kc, s_stop;

    for (int ww = t; ww < MASK_WORDS; ww += 32)
        svb[ww] = ((unsigned long long)g_validbits[2 * ww + 1] << 32) |
                  (unsigned long long)g_validbits[2 * ww];
    if (t < PWORDS) remv[t] = 0ULL;
    for (int j = t; j < 64; j += 32) {
        colbuf[0][j] = g_maskP[(size_t)j * PWORDS + 0];
        colbox[0][j] = g_boxesS[j];
    }
    if (t == 0) { s_kc = 0; s_stop = 0; }
    __syncwarp();

    int kcount = 0;
    for (int w = 0; w < PWORDS; w++) {
        int cur = w & 1, nxt = cur ^ 1;
        if (w + 1 < PWORDS) {
            int nb = (w + 1) * 64;
            for (int j = t; j < 64; j += 32) {
                colbuf[nxt][j] = __ldg(&g_maskP[(size_t)(nb + j) * PWORDS + (w + 1)]);
                colbox[nxt][j] = g_boxesS[nb + j];
            }
        }
        if (t == 0) {
            unsigned long long bits = svb[w] & ~remv[w];
            int nk = 0;
            while (bits) {
                int ib = __ffsll(bits) - 1;
                bits &= bits - 1;
                float4 b = colbox[cur][ib];
                out[kcount * 5 + 0] = 0.f;
                out[kcount * 5 + 1] = b.x;
                out[kcount * 5 + 2] = b.y;
                out[kcount * 5 + 3] = b.z;
                out[kcount * 5 + 4] = b.w;
                skept[kcount] = b;
                skarea[kcount] = (b.z - b.x) * (b.w - b.y);
                s_kept[nk++] = w * 64 + ib;
                kcount++;
                if (kcount >= POST_NMS) { s_stop = 1; break; }
                bits &= ~colbuf[cur][ib];     // intra-word suppression
            }
            s_nk = nk;
            s_kc = kcount;
        }
        __syncwarp();
        if (s_stop) break;
        int nk = s_nk;
        if (nk > 0 && t > 0) {
            for (int ww = w + t; ww < PWORDS; ww += 31) {
                unsigned long long acc = 0ULL;
                for (int k = 0; k < nk; k++)
                    acc |= __ldg(&g_maskP[(size_t)s_kept[k] * PWORDS + ww]);
                remv[ww] |= acc;
            }
        }
        __syncwarp();
    }
    __syncwarp();

    // ---- fallback: candidates beyond PREFIX (normally zero iterations do work) ----
    int kc = s_kc;
    if (kc < POST_NMS) {
        for (int i = PREFIX; i < PRE_NMS; i++) {
            if (!((svb[i >> 6] >> (i & 63)) & 1ULL)) continue;
            float4 b = __ldg(&g_boxesS[i]);          // broadcast load
            float areaI = (b.z - b.x) * (b.w - b.y);
            bool flag = false;
            for (int k = t; k < kc; k += 32) {
                float4 kb = skept[k];
                float lx = fmaxf(b.x, kb.x);
                float ly = fmaxf(b.y, kb.y);
                float rx = fminf(b.z, kb.z);
                float ry = fminf(b.w, kb.w);
                float ww = fmaxf(rx - lx, 0.f);
                float hh = fmaxf(ry - ly, 0.f);
                float inter = ww * hh;
                float iou = inter / (areaI + skarea[k] - inter);
                flag |= (iou > NMS_THR);
            }
            bool supp = __any_sync(0xffffffffu, flag);
            if (!supp) {
                if (t == 0) {
                    skept[kc] = b;
                    skarea[kc] = areaI;
                    out[kc * 5 + 0] = 0.f;
                    out[kc * 5 + 1] = b.x;
                    out[kc * 5 + 2] = b.y;
                    out[kc * 5 + 3] = b.z;
                    out[kc * 5 + 4] = b.w;
                }
                kc++;
                __syncwarp();
                if (kc >= POST_NMS) break;
            }
        }
    }
    __syncwarp();
    // zero-fill remaining rows (kc uniform)
    for (int x = kc * 5 + t; x < POST_NMS * 5; x += 32) out[x] = 0.f;
}

// ============================================================ launch
extern "C" void kernel_launch(void* const* d_in, const int* in_sizes, int n_in,
                              void* d_out, int out_size) {
    const float* scores  = (const float*)d_in[0];
    const float* deltas  = (const float*)d_in[1];
    const float* im_info = (const float*)d_in[2];
    float* out = (float*)d_out;

    k_prep<<<PREP_BLOCKS, 256>>>(scores, deltas, im_info);
    k_rank<<<RANK_BLOCKS, RANK_T>>>();
    dim3 mgrid(PWORDS, PWORDS);
    k_mask_scan<<<mgrid, 64>>>(out);
}